// round 1
// baseline (speedup 1.0000x reference)
#include <cuda_runtime.h>
#include <math.h>

#define B_   16
#define LQ_  1024
#define D_   256
#define H_   8
#define DH_  32
#define L_   4
#define P_   4
#define DFF_ 1024
#define LV_  5440
#define BLQ  (B_*LQ_)   // 16384
#define BLV  (B_*LV_)   // 87040

// ---------------- scratch (static device globals; no runtime allocation) ----
__device__ float g_q   [BLQ*D_];       // tgt+query_pos (q, later q2)
__device__ float g_qk  [BLQ*2*D_];     // q,k projections concatenated (cols 0..511)
__device__ float g_v   [BLQ*D_];       // v projection
__device__ float g_attn[BLQ*D_];       // attention output
__device__ float g_proj[BLQ*D_];       // generic projection result
__device__ float g_tgt1[BLQ*D_];       // after norm2
__device__ float g_tgt2[BLQ*D_];       // after norm1
__device__ float g_val [BLV*D_];       // deform value  [B, LV, H, DH]
__device__ float g_off [BLQ*D_];       // offsets [BLQ, H*L*P*2]
__device__ float g_attw[BLQ*H_*L_*P_]; // attention weights [BLQ, 128]
__device__ float g_samp[BLQ*D_];       // sampled output
__device__ float g_hid [BLQ*DFF_];     // FFN hidden

// ---------------- elementwise add (float4) ---------------------------------
__global__ void add_kernel(const float* __restrict__ a, const float* __restrict__ b,
                           float* __restrict__ o, int n4) {
    int i = blockIdx.x * blockDim.x + threadIdx.x;
    if (i >= n4) return;
    float4 x = reinterpret_cast<const float4*>(a)[i];
    float4 y = reinterpret_cast<const float4*>(b)[i];
    x.x += y.x; x.y += y.y; x.z += y.z; x.w += y.w;
    reinterpret_cast<float4*>(o)[i] = x;
}

// ---------------- SGEMM: C[M,N] = A[M,K] @ W[N,K]^T + bias (opt relu) ------
// BM=BN=128, BK=16, 256 threads, 8x8 microtile.
__global__ __launch_bounds__(256) void sgemm_bias(
    const float* __restrict__ A, const float* __restrict__ W,
    const float* __restrict__ bias, float* __restrict__ C,
    int M, int N, int K, int doRelu)
{
    __shared__ float As[16][129];
    __shared__ float Ws[16][129];
    const int tid = threadIdx.x;
    const int bm = blockIdx.y * 128, bn = blockIdx.x * 128;
    const int tx = tid & 15, ty = tid >> 4;
    const int lk = tid & 15, lr = tid >> 4;

    float acc[8][8];
    #pragma unroll
    for (int i = 0; i < 8; i++)
        #pragma unroll
        for (int j = 0; j < 8; j++) acc[i][j] = 0.f;

    for (int k0 = 0; k0 < K; k0 += 16) {
        #pragma unroll
        for (int r = 0; r < 128; r += 16)
            As[lk][r + lr] = A[(size_t)(bm + r + lr) * K + k0 + lk];
        #pragma unroll
        for (int r = 0; r < 128; r += 16)
            Ws[lk][r + lr] = W[(size_t)(bn + r + lr) * K + k0 + lk];
        __syncthreads();
        #pragma unroll
        for (int k = 0; k < 16; k++) {
            float a[8], w[8];
            #pragma unroll
            for (int i = 0; i < 8; i++) a[i] = As[k][ty * 8 + i];
            #pragma unroll
            for (int j = 0; j < 8; j++) w[j] = Ws[k][tx * 8 + j];
            #pragma unroll
            for (int i = 0; i < 8; i++)
                #pragma unroll
                for (int j = 0; j < 8; j++)
                    acc[i][j] = fmaf(a[i], w[j], acc[i][j]);
        }
        __syncthreads();
    }
    #pragma unroll
    for (int i = 0; i < 8; i++) {
        size_t row = (size_t)(bm + ty * 8 + i);
        #pragma unroll
        for (int j = 0; j < 8; j++) {
            int col = bn + tx * 8 + j;
            float v = acc[i][j] + bias[col];
            if (doRelu) v = fmaxf(v, 0.f);
            C[row * N + col] = v;
        }
    }
}

// ---------------- flash attention (fp32), DH=32 -----------------------------
// grid: (LQ/128, B*H), block 128. Each thread owns one query row.
__global__ __launch_bounds__(128) void attn_kernel(
    const float* __restrict__ qk, const float* __restrict__ vbuf,
    float* __restrict__ out)
{
    const float scale = 0.17677669529663689f; // 1/sqrt(32)
    const int bh = blockIdx.y;
    const int b = bh >> 3, h = bh & 7;
    const int qbase = blockIdx.x * 128;
    const int tid = threadIdx.x;

    __shared__ float Ks[128][36];
    __shared__ float Vs[128][36];

    float4 q4[8];
    {
        const float4* qp = reinterpret_cast<const float4*>(
            qk + (size_t)(b * LQ_ + qbase + tid) * 512 + h * 32);
        #pragma unroll
        for (int i = 0; i < 8; i++) q4[i] = qp[i];
    }
    float4 o4[8];
    #pragma unroll
    for (int i = 0; i < 8; i++) o4[i] = make_float4(0.f, 0.f, 0.f, 0.f);
    float m = -1e30f, l = 0.f;

    for (int kb = 0; kb < LQ_; kb += 128) {
        for (int idx = tid; idx < 128 * 32; idx += 128) {
            int row = idx >> 5, d = idx & 31;
            Ks[row][d] = qk[(size_t)(b * LQ_ + kb + row) * 512 + 256 + h * 32 + d];
            Vs[row][d] = vbuf[(size_t)(b * LQ_ + kb + row) * 256 + h * 32 + d];
        }
        __syncthreads();
        #pragma unroll 1
        for (int j0 = 0; j0 < 128; j0 += 16) {
            float s[16];
            float cmax = -1e30f;
            #pragma unroll
            for (int j = 0; j < 16; j++) {
                const float4* kp = reinterpret_cast<const float4*>(&Ks[j0 + j][0]);
                float acc = 0.f;
                #pragma unroll
                for (int i = 0; i < 8; i++) {
                    float4 kv = kp[i];
                    acc = fmaf(q4[i].x, kv.x, acc);
                    acc = fmaf(q4[i].y, kv.y, acc);
                    acc = fmaf(q4[i].z, kv.z, acc);
                    acc = fmaf(q4[i].w, kv.w, acc);
                }
                s[j] = acc * scale;
                cmax = fmaxf(cmax, s[j]);
            }
            float mnew = fmaxf(m, cmax);
            float corr = __expf(m - mnew);
            l *= corr;
            #pragma unroll
            for (int i = 0; i < 8; i++) {
                o4[i].x *= corr; o4[i].y *= corr; o4[i].z *= corr; o4[i].w *= corr;
            }
            #pragma unroll
            for (int j = 0; j < 16; j++) {
                float p = __expf(s[j] - mnew);
                l += p;
                const float4* vp = reinterpret_cast<const float4*>(&Vs[j0 + j][0]);
                #pragma unroll
                for (int i = 0; i < 8; i++) {
                    float4 vv = vp[i];
                    o4[i].x = fmaf(p, vv.x, o4[i].x);
                    o4[i].y = fmaf(p, vv.y, o4[i].y);
                    o4[i].z = fmaf(p, vv.z, o4[i].z);
                    o4[i].w = fmaf(p, vv.w, o4[i].w);
                }
            }
            m = mnew;
        }
        __syncthreads();
    }
    float inv = 1.f / l;
    float* op = out + (size_t)(b * LQ_ + qbase + tid) * 256 + h * 32;
    #pragma unroll
    for (int i = 0; i < 8; i++) {
        float4 r = o4[i];
        r.x *= inv; r.y *= inv; r.z *= inv; r.w *= inv;
        reinterpret_cast<float4*>(op)[i] = r;
    }
}

// ---------------- fused residual + LayerNorm (D=256) ------------------------
__global__ __launch_bounds__(256) void add_ln_kernel(
    const float* __restrict__ a, const float* __restrict__ b,
    const float* __restrict__ g, const float* __restrict__ bet,
    float* __restrict__ out)
{
    int row = blockIdx.x;
    int t = threadIdx.x;
    size_t base = (size_t)row * 256;
    float x = a[base + t] + b[base + t];
    float s = x, sq = x * x;
    #pragma unroll
    for (int o = 16; o > 0; o >>= 1) {
        s  += __shfl_xor_sync(0xffffffffu, s, o);
        sq += __shfl_xor_sync(0xffffffffu, sq, o);
    }
    __shared__ float ss[8], ssq[8];
    int w = t >> 5, ln = t & 31;
    if (ln == 0) { ss[w] = s; ssq[w] = sq; }
    __syncthreads();
    float tot = 0.f, totq = 0.f;
    #pragma unroll
    for (int i = 0; i < 8; i++) { tot += ss[i]; totq += ssq[i]; }
    float mean = tot * (1.f / 256.f);
    float var  = totq * (1.f / 256.f) - mean * mean;
    out[base + t] = (x - mean) * rsqrtf(var + 1e-5f) * g[t] + bet[t];
}

// ---------------- softmax over 16 (per b,q,h) -------------------------------
__global__ void softmax16_kernel(float* __restrict__ w, int n) {
    int i = blockIdx.x * blockDim.x + threadIdx.x;
    if (i >= n) return;
    float4* p = reinterpret_cast<float4*>(w + (size_t)i * 16);
    float4 v[4];
    #pragma unroll
    for (int j = 0; j < 4; j++) v[j] = p[j];
    float mx = -1e30f;
    #pragma unroll
    for (int j = 0; j < 4; j++) {
        mx = fmaxf(mx, fmaxf(fmaxf(v[j].x, v[j].y), fmaxf(v[j].z, v[j].w)));
    }
    float sum = 0.f;
    #pragma unroll
    for (int j = 0; j < 4; j++) {
        v[j].x = __expf(v[j].x - mx); sum += v[j].x;
        v[j].y = __expf(v[j].y - mx); sum += v[j].y;
        v[j].z = __expf(v[j].z - mx); sum += v[j].z;
        v[j].w = __expf(v[j].w - mx); sum += v[j].w;
    }
    float inv = 1.f / sum;
    #pragma unroll
    for (int j = 0; j < 4; j++) {
        v[j].x *= inv; v[j].y *= inv; v[j].z *= inv; v[j].w *= inv;
        p[j] = v[j];
    }
}

// ---------------- deformable sampling ---------------------------------------
__device__ __forceinline__ float dtap(const float* __restrict__ value,
                                      int b, int start, int hl, int wl,
                                      int xi, int yi, int h, int lane) {
    if (xi < 0 || xi >= wl || yi < 0 || yi >= hl) return 0.f;
    int row = start + yi * wl + xi;
    return value[((size_t)(b * LV_ + row) * 8 + h) * 32 + lane];
}

// warp per (b,q,h); lane = dh
__global__ __launch_bounds__(128) void deform_kernel(
    const float* __restrict__ refp, const float* __restrict__ off,
    const float* __restrict__ attw, const float* __restrict__ value,
    float* __restrict__ out)
{
    int wid = blockIdx.x * 4 + (threadIdx.x >> 5);
    int lane = threadIdx.x & 31;
    int h = wid & 7;
    int bq = wid >> 3;
    int b = bq >> 10;
    const int HLs[4] = {64, 32, 16, 8};
    float acc = 0.f;
    int start = 0;
    #pragma unroll
    for (int lvl = 0; lvl < 4; lvl++) {
        int hl = HLs[lvl], wl = HLs[lvl];
        float fwl = (float)wl, fhl = (float)hl;
        float refx = refp[(bq * 4 + lvl) * 2 + 0];
        float refy = refp[(bq * 4 + lvl) * 2 + 1];
        #pragma unroll
        for (int p = 0; p < 4; p++) {
            int oi = bq * 256 + ((h * 4 + lvl) * 4 + p) * 2;
            float ox = off[oi], oy = off[oi + 1];
            float aw = attw[(bq * 8 + h) * 16 + lvl * 4 + p];
            float locx = refx + ox / fwl;
            float locy = refy + oy / fhl;
            float x = locx * fwl - 0.5f;
            float y = locy * fhl - 0.5f;
            float x0 = floorf(x), y0 = floorf(y);
            float lx = x - x0, ly = y - y0;
            int x0i = (int)x0, y0i = (int)y0;
            float v00 = dtap(value, b, start, hl, wl, x0i,     y0i,     h, lane);
            float v01 = dtap(value, b, start, hl, wl, x0i + 1, y0i,     h, lane);
            float v10 = dtap(value, b, start, hl, wl, x0i,     y0i + 1, h, lane);
            float v11 = dtap(value, b, start, hl, wl, x0i + 1, y0i + 1, h, lane);
            float sx = v00 * (1.f - lx) * (1.f - ly) + v01 * lx * (1.f - ly)
                     + v10 * (1.f - lx) * ly         + v11 * lx * ly;
            acc = fmaf(aw, sx, acc);
        }
        start += hl * wl;
    }
    out[(size_t)bq * 256 + h * 32 + lane] = acc;
}

// ---------------- launcher ---------------------------------------------------
extern "C" void kernel_launch(void* const* d_in, const int* in_sizes, int n_in,
                              void* d_out, int out_size)
{
    const float* tgt       = (const float*)d_in[0];
    const float* query_pos = (const float*)d_in[1];
    const float* refp      = (const float*)d_in[2];
    const float* src       = (const float*)d_in[3];
    const float* in_proj_w = (const float*)d_in[4];
    const float* in_proj_b = (const float*)d_in[5];
    const float* out_proj_w= (const float*)d_in[6];
    const float* out_proj_b= (const float*)d_in[7];
    const float* norm2_g   = (const float*)d_in[8];
    const float* norm2_b   = (const float*)d_in[9];
    const float* value_w   = (const float*)d_in[10];
    const float* value_b   = (const float*)d_in[11];
    const float* off_w     = (const float*)d_in[12];
    const float* off_b     = (const float*)d_in[13];
    const float* attw_w    = (const float*)d_in[14];
    const float* attw_b    = (const float*)d_in[15];
    const float* outp_w    = (const float*)d_in[16];
    const float* outp_b    = (const float*)d_in[17];
    const float* norm1_g   = (const float*)d_in[18];
    const float* norm1_b   = (const float*)d_in[19];
    const float* lin1_w    = (const float*)d_in[20];
    const float* lin1_b    = (const float*)d_in[21];
    const float* lin2_w    = (const float*)d_in[22];
    const float* lin2_b    = (const float*)d_in[23];
    const float* norm3_g   = (const float*)d_in[24];
    const float* norm3_b   = (const float*)d_in[25];
    float* outp = (float*)d_out;

    float *q_, *qk_, *v_, *attn_, *proj_, *tgt1_, *tgt2_, *val_, *off_, *attw_, *samp_, *hid_;
    cudaGetSymbolAddress((void**)&q_,    g_q);
    cudaGetSymbolAddress((void**)&qk_,   g_qk);
    cudaGetSymbolAddress((void**)&v_,    g_v);
    cudaGetSymbolAddress((void**)&attn_, g_attn);
    cudaGetSymbolAddress((void**)&proj_, g_proj);
    cudaGetSymbolAddress((void**)&tgt1_, g_tgt1);
    cudaGetSymbolAddress((void**)&tgt2_, g_tgt2);
    cudaGetSymbolAddress((void**)&val_,  g_val);
    cudaGetSymbolAddress((void**)&off_,  g_off);
    cudaGetSymbolAddress((void**)&attw_, g_attw);
    cudaGetSymbolAddress((void**)&samp_, g_samp);
    cudaGetSymbolAddress((void**)&hid_,  g_hid);

    const int n4 = (BLQ * D_) / 4;

    // q = tgt + query_pos
    add_kernel<<<(n4 + 255) / 256, 256>>>(tgt, query_pos, q_, n4);
    // q,k projections: [BLQ,256] @ [512,256]^T
    sgemm_bias<<<dim3(4, BLQ / 128), 256>>>(q_, in_proj_w, in_proj_b, qk_, BLQ, 512, 256, 0);
    // v projection from tgt: rows 512..767 of in_proj_w
    sgemm_bias<<<dim3(2, BLQ / 128), 256>>>(tgt, in_proj_w + 512 * 256, in_proj_b + 512, v_, BLQ, 256, 256, 0);
    // flash attention
    attn_kernel<<<dim3(LQ_ / 128, B_ * H_), 128>>>(qk_, v_, attn_);
    // output projection
    sgemm_bias<<<dim3(2, BLQ / 128), 256>>>(attn_, out_proj_w, out_proj_b, proj_, BLQ, 256, 256, 0);
    // norm2: tgt1 = LN(tgt + proj)
    add_ln_kernel<<<BLQ, 256>>>(tgt, proj_, norm2_g, norm2_b, tgt1_);
    // q2 = tgt1 + query_pos
    add_kernel<<<(n4 + 255) / 256, 256>>>(tgt1_, query_pos, q_, n4);
    // value projection [BLV,256]
    sgemm_bias<<<dim3(2, BLV / 128), 256>>>(src, value_w, value_b, val_, BLV, 256, 256, 0);
    // offsets + attention weights
    sgemm_bias<<<dim3(2, BLQ / 128), 256>>>(q_, off_w, off_b, off_, BLQ, 256, 256, 0);
    sgemm_bias<<<dim3(1, BLQ / 128), 256>>>(q_, attw_w, attw_b, attw_, BLQ, 128, 256, 0);
    softmax16_kernel<<<(BLQ * H_) / 256, 256>>>(attw_, BLQ * H_);
    // deformable sampling
    deform_kernel<<<(BLQ * H_) / 4, 128>>>(refp, off_, attw_, val_, samp_);
    // ms-deform output projection
    sgemm_bias<<<dim3(2, BLQ / 128), 256>>>(samp_, outp_w, outp_b, proj_, BLQ, 256, 256, 0);
    // norm1: tgt2 = LN(tgt1 + proj)
    add_ln_kernel<<<BLQ, 256>>>(tgt1_, proj_, norm1_g, norm1_b, tgt2_);
    // FFN
    sgemm_bias<<<dim3(8, BLQ / 128), 256>>>(tgt2_, lin1_w, lin1_b, hid_, BLQ, 1024, 256, 1);
    sgemm_bias<<<dim3(2, BLQ / 128), 256>>>(hid_, lin2_w, lin2_b, proj_, BLQ, 256, 1024, 0);
    // norm3 -> final output
    add_ln_kernel<<<BLQ, 256>>>(tgt2_, proj_, norm3_g, norm3_b, outp);
}

// round 2
// speedup vs baseline: 2.1038x; 2.1038x over previous
#include <cuda_runtime.h>
#include <math.h>
#include <stdint.h>

#define B_   16
#define LQ_  1024
#define D_   256
#define H_   8
#define DH_  32
#define L_   4
#define P_   4
#define DFF_ 1024
#define LV_  5440
#define BLQ  (B_*LQ_)   // 16384
#define BLV  (B_*LV_)   // 87040

// ---------------- scratch (static device globals; no runtime allocation) ----
__device__ float g_q   [BLQ*D_];
__device__ float g_qk  [BLQ*2*D_];
__device__ float g_v   [BLQ*D_];
__device__ float g_attn[BLQ*D_];
__device__ float g_proj[BLQ*D_];
__device__ float g_tgt1[BLQ*D_];
__device__ float g_tgt2[BLQ*D_];
__device__ float g_val [BLV*D_];
__device__ float g_off [BLQ*D_];
__device__ float g_attw[BLQ*H_*L_*P_];
__device__ float g_samp[BLQ*D_];
__device__ float g_hid [BLQ*DFF_];

// ---------------- elementwise add (float4) ---------------------------------
__global__ void add_kernel(const float* __restrict__ a, const float* __restrict__ b,
                           float* __restrict__ o, int n4) {
    int i = blockIdx.x * blockDim.x + threadIdx.x;
    if (i >= n4) return;
    float4 x = reinterpret_cast<const float4*>(a)[i];
    float4 y = reinterpret_cast<const float4*>(b)[i];
    x.x += y.x; x.y += y.y; x.z += y.z; x.w += y.w;
    reinterpret_cast<float4*>(o)[i] = x;
}

// ---------------- tf32 helpers ----------------------------------------------
__device__ __forceinline__ uint32_t f2tf(float x) {
    uint32_t r;
    asm("cvt.rna.tf32.f32 %0, %1;" : "=r"(r) : "f"(x));
    return r;
}

__device__ __forceinline__ void mma_tf32(float c[4], const uint32_t a[4], const uint32_t b[2]) {
    asm volatile(
        "mma.sync.aligned.m16n8k8.row.col.f32.tf32.tf32.f32 "
        "{%0,%1,%2,%3}, {%4,%5,%6,%7}, {%8,%9}, {%0,%1,%2,%3};"
        : "+f"(c[0]), "+f"(c[1]), "+f"(c[2]), "+f"(c[3])
        : "r"(a[0]), "r"(a[1]), "r"(a[2]), "r"(a[3]),
          "r"(b[0]), "r"(b[1]));
}

// ---------------- tf32 tensor-core GEMM: C = A[M,K] @ W[N,K]^T + bias -------
// BM=128, BN=128, BK=16, 256 threads (8 warps, 4m x 2n), warp tile 32x64.
// smem layout [row][k] with padded stride 20: verified conflict-free for the
// m16n8k8 fragment pattern (banks (20*grp+q)%32 are all distinct).
__global__ __launch_bounds__(256) void sgemm_tf32(
    const float* __restrict__ A, const float* __restrict__ W,
    const float* __restrict__ bias, float* __restrict__ C,
    int M, int N, int K, int doRelu)
{
    __shared__ uint32_t As[128][20];
    __shared__ uint32_t Ws[128][20];

    const int tid = threadIdx.x;
    const int bm = blockIdx.y * 128, bn = blockIdx.x * 128;
    const int warp = tid >> 5, lane = tid & 31;
    const int wm = warp & 3, wn = warp >> 2;       // 4 x 2 warp grid
    const int grp = lane >> 2, q = lane & 3;

    const int ldrow = tid >> 1;
    const int ldc0  = (tid & 1) * 8;

    float c[2][8][4];
    #pragma unroll
    for (int mi = 0; mi < 2; mi++)
        #pragma unroll
        for (int ni = 0; ni < 8; ni++)
            #pragma unroll
            for (int r = 0; r < 4; r++) c[mi][ni][r] = 0.f;

    for (int k0 = 0; k0 < K; k0 += 16) {
        // load A tile (128x16) and W tile (128x16), convert to tf32 (rna)
        {
            const float4* ap = reinterpret_cast<const float4*>(
                &A[(size_t)(bm + ldrow) * K + k0 + ldc0]);
            float4 v0 = ap[0], v1 = ap[1];
            As[ldrow][ldc0 + 0] = f2tf(v0.x);
            As[ldrow][ldc0 + 1] = f2tf(v0.y);
            As[ldrow][ldc0 + 2] = f2tf(v0.z);
            As[ldrow][ldc0 + 3] = f2tf(v0.w);
            As[ldrow][ldc0 + 4] = f2tf(v1.x);
            As[ldrow][ldc0 + 5] = f2tf(v1.y);
            As[ldrow][ldc0 + 6] = f2tf(v1.z);
            As[ldrow][ldc0 + 7] = f2tf(v1.w);
            const float4* wp = reinterpret_cast<const float4*>(
                &W[(size_t)(bn + ldrow) * K + k0 + ldc0]);
            float4 w0 = wp[0], w1 = wp[1];
            Ws[ldrow][ldc0 + 0] = f2tf(w0.x);
            Ws[ldrow][ldc0 + 1] = f2tf(w0.y);
            Ws[ldrow][ldc0 + 2] = f2tf(w0.z);
            Ws[ldrow][ldc0 + 3] = f2tf(w0.w);
            Ws[ldrow][ldc0 + 4] = f2tf(w1.x);
            Ws[ldrow][ldc0 + 5] = f2tf(w1.y);
            Ws[ldrow][ldc0 + 6] = f2tf(w1.z);
            Ws[ldrow][ldc0 + 7] = f2tf(w1.w);
        }
        __syncthreads();

        #pragma unroll
        for (int ks = 0; ks < 2; ks++) {
            const int kb = ks * 8;
            uint32_t af[2][4];
            #pragma unroll
            for (int mi = 0; mi < 2; mi++) {
                int m = wm * 32 + mi * 16 + grp;
                af[mi][0] = As[m    ][kb + q];
                af[mi][1] = As[m + 8][kb + q];
                af[mi][2] = As[m    ][kb + q + 4];
                af[mi][3] = As[m + 8][kb + q + 4];
            }
            uint32_t bf[8][2];
            #pragma unroll
            for (int ni = 0; ni < 8; ni++) {
                int n = wn * 64 + ni * 8 + grp;
                bf[ni][0] = Ws[n][kb + q];
                bf[ni][1] = Ws[n][kb + q + 4];
            }
            #pragma unroll
            for (int mi = 0; mi < 2; mi++)
                #pragma unroll
                for (int ni = 0; ni < 8; ni++)
                    mma_tf32(c[mi][ni], af[mi], bf[ni]);
        }
        __syncthreads();
    }

    // epilogue: bias (+relu), float2 stores
    #pragma unroll
    for (int mi = 0; mi < 2; mi++) {
        int r0 = bm + wm * 32 + mi * 16 + grp;
        #pragma unroll
        for (int ni = 0; ni < 8; ni++) {
            int col = bn + wn * 64 + ni * 8 + 2 * q;
            float b0 = bias[col], b1 = bias[col + 1];
            float v0 = c[mi][ni][0] + b0;
            float v1 = c[mi][ni][1] + b1;
            float v2 = c[mi][ni][2] + b0;
            float v3 = c[mi][ni][3] + b1;
            if (doRelu) {
                v0 = fmaxf(v0, 0.f); v1 = fmaxf(v1, 0.f);
                v2 = fmaxf(v2, 0.f); v3 = fmaxf(v3, 0.f);
            }
            reinterpret_cast<float2*>(&C[(size_t)r0 * N + col])[0]       = make_float2(v0, v1);
            reinterpret_cast<float2*>(&C[(size_t)(r0 + 8) * N + col])[0] = make_float2(v2, v3);
        }
    }
}

// ---------------- flash attention (fp32), DH=32 -----------------------------
__global__ __launch_bounds__(128) void attn_kernel(
    const float* __restrict__ qk, const float* __restrict__ vbuf,
    float* __restrict__ out)
{
    const float scale = 0.17677669529663689f; // 1/sqrt(32)
    const int bh = blockIdx.y;
    const int b = bh >> 3, h = bh & 7;
    const int qbase = blockIdx.x * 128;
    const int tid = threadIdx.x;

    __shared__ float Ks[128][36];
    __shared__ float Vs[128][36];

    float4 q4[8];
    {
        const float4* qp = reinterpret_cast<const float4*>(
            qk + (size_t)(b * LQ_ + qbase + tid) * 512 + h * 32);
        #pragma unroll
        for (int i = 0; i < 8; i++) q4[i] = qp[i];
    }
    float4 o4[8];
    #pragma unroll
    for (int i = 0; i < 8; i++) o4[i] = make_float4(0.f, 0.f, 0.f, 0.f);
    float m = -1e30f, l = 0.f;

    for (int kb = 0; kb < LQ_; kb += 128) {
        for (int idx = tid; idx < 128 * 32; idx += 128) {
            int row = idx >> 5, d = idx & 31;
            Ks[row][d] = qk[(size_t)(b * LQ_ + kb + row) * 512 + 256 + h * 32 + d];
            Vs[row][d] = vbuf[(size_t)(b * LQ_ + kb + row) * 256 + h * 32 + d];
        }
        __syncthreads();
        #pragma unroll 1
        for (int j0 = 0; j0 < 128; j0 += 16) {
            float s[16];
            float cmax = -1e30f;
            #pragma unroll
            for (int j = 0; j < 16; j++) {
                const float4* kp = reinterpret_cast<const float4*>(&Ks[j0 + j][0]);
                float acc = 0.f;
                #pragma unroll
                for (int i = 0; i < 8; i++) {
                    float4 kv = kp[i];
                    acc = fmaf(q4[i].x, kv.x, acc);
                    acc = fmaf(q4[i].y, kv.y, acc);
                    acc = fmaf(q4[i].z, kv.z, acc);
                    acc = fmaf(q4[i].w, kv.w, acc);
                }
                s[j] = acc * scale;
                cmax = fmaxf(cmax, s[j]);
            }
            float mnew = fmaxf(m, cmax);
            float corr = __expf(m - mnew);
            l *= corr;
            #pragma unroll
            for (int i = 0; i < 8; i++) {
                o4[i].x *= corr; o4[i].y *= corr; o4[i].z *= corr; o4[i].w *= corr;
            }
            #pragma unroll
            for (int j = 0; j < 16; j++) {
                float p = __expf(s[j] - mnew);
                l += p;
                const float4* vp = reinterpret_cast<const float4*>(&Vs[j0 + j][0]);
                #pragma unroll
                for (int i = 0; i < 8; i++) {
                    float4 vv = vp[i];
                    o4[i].x = fmaf(p, vv.x, o4[i].x);
                    o4[i].y = fmaf(p, vv.y, o4[i].y);
                    o4[i].z = fmaf(p, vv.z, o4[i].z);
                    o4[i].w = fmaf(p, vv.w, o4[i].w);
                }
            }
            m = mnew;
        }
        __syncthreads();
    }
    float inv = 1.f / l;
    float* op = out + (size_t)(b * LQ_ + qbase + tid) * 256 + h * 32;
    #pragma unroll
    for (int i = 0; i < 8; i++) {
        float4 r = o4[i];
        r.x *= inv; r.y *= inv; r.z *= inv; r.w *= inv;
        reinterpret_cast<float4*>(op)[i] = r;
    }
}

// ---------------- fused residual + LayerNorm (D=256) ------------------------
__global__ __launch_bounds__(256) void add_ln_kernel(
    const float* __restrict__ a, const float* __restrict__ b,
    const float* __restrict__ g, const float* __restrict__ bet,
    float* __restrict__ out)
{
    int row = blockIdx.x;
    int t = threadIdx.x;
    size_t base = (size_t)row * 256;
    float x = a[base + t] + b[base + t];
    float s = x, sq = x * x;
    #pragma unroll
    for (int o = 16; o > 0; o >>= 1) {
        s  += __shfl_xor_sync(0xffffffffu, s, o);
        sq += __shfl_xor_sync(0xffffffffu, sq, o);
    }
    __shared__ float ss[8], ssq[8];
    int w = t >> 5, ln = t & 31;
    if (ln == 0) { ss[w] = s; ssq[w] = sq; }
    __syncthreads();
    float tot = 0.f, totq = 0.f;
    #pragma unroll
    for (int i = 0; i < 8; i++) { tot += ss[i]; totq += ssq[i]; }
    float mean = tot * (1.f / 256.f);
    float var  = totq * (1.f / 256.f) - mean * mean;
    out[base + t] = (x - mean) * rsqrtf(var + 1e-5f) * g[t] + bet[t];
}

// ---------------- softmax over 16 (per b,q,h) -------------------------------
__global__ void softmax16_kernel(float* __restrict__ w, int n) {
    int i = blockIdx.x * blockDim.x + threadIdx.x;
    if (i >= n) return;
    float4* p = reinterpret_cast<float4*>(w + (size_t)i * 16);
    float4 v[4];
    #pragma unroll
    for (int j = 0; j < 4; j++) v[j] = p[j];
    float mx = -1e30f;
    #pragma unroll
    for (int j = 0; j < 4; j++) {
        mx = fmaxf(mx, fmaxf(fmaxf(v[j].x, v[j].y), fmaxf(v[j].z, v[j].w)));
    }
    float sum = 0.f;
    #pragma unroll
    for (int j = 0; j < 4; j++) {
        v[j].x = __expf(v[j].x - mx); sum += v[j].x;
        v[j].y = __expf(v[j].y - mx); sum += v[j].y;
        v[j].z = __expf(v[j].z - mx); sum += v[j].z;
        v[j].w = __expf(v[j].w - mx); sum += v[j].w;
    }
    float inv = 1.f / sum;
    #pragma unroll
    for (int j = 0; j < 4; j++) {
        v[j].x *= inv; v[j].y *= inv; v[j].z *= inv; v[j].w *= inv;
        p[j] = v[j];
    }
}

// ---------------- deformable sampling ---------------------------------------
__device__ __forceinline__ float dtap(const float* __restrict__ value,
                                      int b, int start, int hl, int wl,
                                      int xi, int yi, int h, int lane) {
    if (xi < 0 || xi >= wl || yi < 0 || yi >= hl) return 0.f;
    int row = start + yi * wl + xi;
    return value[((size_t)(b * LV_ + row) * 8 + h) * 32 + lane];
}

__global__ __launch_bounds__(128) void deform_kernel(
    const float* __restrict__ refp, const float* __restrict__ off,
    const float* __restrict__ attw, const float* __restrict__ value,
    float* __restrict__ out)
{
    int wid = blockIdx.x * 4 + (threadIdx.x >> 5);
    int lane = threadIdx.x & 31;
    int h = wid & 7;
    int bq = wid >> 3;
    int b = bq >> 10;
    const int HLs[4] = {64, 32, 16, 8};
    float acc = 0.f;
    int start = 0;
    #pragma unroll
    for (int lvl = 0; lvl < 4; lvl++) {
        int hl = HLs[lvl], wl = HLs[lvl];
        float fwl = (float)wl, fhl = (float)hl;
        float refx = refp[(bq * 4 + lvl) * 2 + 0];
        float refy = refp[(bq * 4 + lvl) * 2 + 1];
        #pragma unroll
        for (int p = 0; p < 4; p++) {
            int oi = bq * 256 + ((h * 4 + lvl) * 4 + p) * 2;
            float ox = off[oi], oy = off[oi + 1];
            float aw = attw[(bq * 8 + h) * 16 + lvl * 4 + p];
            float locx = refx + ox / fwl;
            float locy = refy + oy / fhl;
            float x = locx * fwl - 0.5f;
            float y = locy * fhl - 0.5f;
            float x0 = floorf(x), y0 = floorf(y);
            float lx = x - x0, ly = y - y0;
            int x0i = (int)x0, y0i = (int)y0;
            float v00 = dtap(value, b, start, hl, wl, x0i,     y0i,     h, lane);
            float v01 = dtap(value, b, start, hl, wl, x0i + 1, y0i,     h, lane);
            float v10 = dtap(value, b, start, hl, wl, x0i,     y0i + 1, h, lane);
            float v11 = dtap(value, b, start, hl, wl, x0i + 1, y0i + 1, h, lane);
            float sx = v00 * (1.f - lx) * (1.f - ly) + v01 * lx * (1.f - ly)
                     + v10 * (1.f - lx) * ly         + v11 * lx * ly;
            acc = fmaf(aw, sx, acc);
        }
        start += hl * wl;
    }
    out[(size_t)bq * 256 + h * 32 + lane] = acc;
}

// ---------------- launcher ---------------------------------------------------
extern "C" void kernel_launch(void* const* d_in, const int* in_sizes, int n_in,
                              void* d_out, int out_size)
{
    const float* tgt       = (const float*)d_in[0];
    const float* query_pos = (const float*)d_in[1];
    const float* refp      = (const float*)d_in[2];
    const float* src       = (const float*)d_in[3];
    const float* in_proj_w = (const float*)d_in[4];
    const float* in_proj_b = (const float*)d_in[5];
    const float* out_proj_w= (const float*)d_in[6];
    const float* out_proj_b= (const float*)d_in[7];
    const float* norm2_g   = (const float*)d_in[8];
    const float* norm2_b   = (const float*)d_in[9];
    const float* value_w   = (const float*)d_in[10];
    const float* value_b   = (const float*)d_in[11];
    const float* off_w     = (const float*)d_in[12];
    const float* off_b     = (const float*)d_in[13];
    const float* attw_w    = (const float*)d_in[14];
    const float* attw_b    = (const float*)d_in[15];
    const float* outp_w    = (const float*)d_in[16];
    const float* outp_b    = (const float*)d_in[17];
    const float* norm1_g   = (const float*)d_in[18];
    const float* norm1_b   = (const float*)d_in[19];
    const float* lin1_w    = (const float*)d_in[20];
    const float* lin1_b    = (const float*)d_in[21];
    const float* lin2_w    = (const float*)d_in[22];
    const float* lin2_b    = (const float*)d_in[23];
    const float* norm3_g   = (const float*)d_in[24];
    const float* norm3_b   = (const float*)d_in[25];
    float* outp = (float*)d_out;

    float *q_, *qk_, *v_, *attn_, *proj_, *tgt1_, *tgt2_, *val_, *off_, *attw_, *samp_, *hid_;
    cudaGetSymbolAddress((void**)&q_,    g_q);
    cudaGetSymbolAddress((void**)&qk_,   g_qk);
    cudaGetSymbolAddress((void**)&v_,    g_v);
    cudaGetSymbolAddress((void**)&attn_, g_attn);
    cudaGetSymbolAddress((void**)&proj_, g_proj);
    cudaGetSymbolAddress((void**)&tgt1_, g_tgt1);
    cudaGetSymbolAddress((void**)&tgt2_, g_tgt2);
    cudaGetSymbolAddress((void**)&val_,  g_val);
    cudaGetSymbolAddress((void**)&off_,  g_off);
    cudaGetSymbolAddress((void**)&attw_, g_attw);
    cudaGetSymbolAddress((void**)&samp_, g_samp);
    cudaGetSymbolAddress((void**)&hid_,  g_hid);

    const int n4 = (BLQ * D_) / 4;

    // q = tgt + query_pos
    add_kernel<<<(n4 + 255) / 256, 256>>>(tgt, query_pos, q_, n4);
    // q,k projections: [BLQ,256] @ [512,256]^T
    sgemm_tf32<<<dim3(512 / 128, BLQ / 128), 256>>>(q_, in_proj_w, in_proj_b, qk_, BLQ, 512, 256, 0);
    // v projection from tgt: rows 512..767 of in_proj_w
    sgemm_tf32<<<dim3(2, BLQ / 128), 256>>>(tgt, in_proj_w + 512 * 256, in_proj_b + 512, v_, BLQ, 256, 256, 0);
    // flash attention
    attn_kernel<<<dim3(LQ_ / 128, B_ * H_), 128>>>(qk_, v_, attn_);
    // output projection
    sgemm_tf32<<<dim3(2, BLQ / 128), 256>>>(attn_, out_proj_w, out_proj_b, proj_, BLQ, 256, 256, 0);
    // norm2: tgt1 = LN(tgt + proj)
    add_ln_kernel<<<BLQ, 256>>>(tgt, proj_, norm2_g, norm2_b, tgt1_);
    // q2 = tgt1 + query_pos
    add_kernel<<<(n4 + 255) / 256, 256>>>(tgt1_, query_pos, q_, n4);
    // value projection [BLV,256]
    sgemm_tf32<<<dim3(2, BLV / 128), 256>>>(src, value_w, value_b, val_, BLV, 256, 256, 0);
    // offsets + attention weights
    sgemm_tf32<<<dim3(2, BLQ / 128), 256>>>(q_, off_w, off_b, off_, BLQ, 256, 256, 0);
    sgemm_tf32<<<dim3(1, BLQ / 128), 256>>>(q_, attw_w, attw_b, attw_, BLQ, 128, 256, 0);
    softmax16_kernel<<<(BLQ * H_) / 256, 256>>>(attw_, BLQ * H_);
    // deformable sampling
    deform_kernel<<<(BLQ * H_) / 4, 128>>>(refp, off_, attw_, val_, samp_);
    // ms-deform output projection
    sgemm_tf32<<<dim3(2, BLQ / 128), 256>>>(samp_, outp_w, outp_b, proj_, BLQ, 256, 256, 0);
    // norm1: tgt2 = LN(tgt1 + proj)
    add_ln_kernel<<<BLQ, 256>>>(tgt1_, proj_, norm1_g, norm1_b, tgt2_);
    // FFN
    sgemm_tf32<<<dim3(8, BLQ / 128), 256>>>(tgt2_, lin1_w, lin1_b, hid_, BLQ, 1024, 256, 1);
    sgemm_tf32<<<dim3(2, BLQ / 128), 256>>>(hid_, lin2_w, lin2_b, proj_, BLQ, 256, 1024, 0);
    // norm3 -> final output
    add_ln_kernel<<<BLQ, 256>>>(tgt2_, proj_, norm3_g, norm3_b, outp);
}

// round 4
// speedup vs baseline: 3.0347x; 1.4425x over previous
#include <cuda_runtime.h>
#include <math.h>
#include <stdint.h>

#define B_   16
#define LQ_  1024
#define D_   256
#define H_   8
#define DH_  32
#define L_   4
#define P_   4
#define DFF_ 1024
#define LV_  5440
#define BLQ  (B_*LQ_)   // 16384
#define BLV  (B_*LV_)   // 87040

// ---------------- scratch (static device globals; no runtime allocation) ----
__device__ float g_q   [BLQ*D_];
__device__ float g_qk  [BLQ*2*D_];
__device__ float g_v   [BLQ*D_];
__device__ float g_attn[BLQ*D_];
__device__ float g_proj[BLQ*D_];
__device__ float g_tgt1[BLQ*D_];
__device__ float g_tgt2[BLQ*D_];
__device__ float g_val [BLV*D_];
__device__ float g_off [BLQ*D_];
__device__ float g_attw[BLQ*H_*L_*P_];
__device__ float g_samp[BLQ*D_];
__device__ float g_hid [BLQ*DFF_];

// ---------------- elementwise add (float4) ---------------------------------
__global__ void add_kernel(const float* __restrict__ a, const float* __restrict__ b,
                           float* __restrict__ o, int n4) {
    int i = blockIdx.x * blockDim.x + threadIdx.x;
    if (i >= n4) return;
    float4 x = reinterpret_cast<const float4*>(a)[i];
    float4 y = reinterpret_cast<const float4*>(b)[i];
    x.x += y.x; x.y += y.y; x.z += y.z; x.w += y.w;
    reinterpret_cast<float4*>(o)[i] = x;
}

// ---------------- tf32 helpers ----------------------------------------------
__device__ __forceinline__ uint32_t f2tf(float x) {
    uint32_t r;
    asm("cvt.rna.tf32.f32 %0, %1;" : "=r"(r) : "f"(x));
    return r;
}

__device__ __forceinline__ void mma_tf32(float c[4], const uint32_t a[4], const uint32_t b[2]) {
    asm volatile(
        "mma.sync.aligned.m16n8k8.row.col.f32.tf32.tf32.f32 "
        "{%0,%1,%2,%3}, {%4,%5,%6,%7}, {%8,%9}, {%0,%1,%2,%3};"
        : "+f"(c[0]), "+f"(c[1]), "+f"(c[2]), "+f"(c[3])
        : "r"(a[0]), "r"(a[1]), "r"(a[2]), "r"(a[3]),
          "r"(b[0]), "r"(b[1]));
}

// ---------------- tf32 tensor-core GEMM: C = A[M,K] @ W[N,K]^T + bias -------
__global__ __launch_bounds__(256) void sgemm_tf32(
    const float* __restrict__ A, const float* __restrict__ W,
    const float* __restrict__ bias, float* __restrict__ C,
    int M, int N, int K, int doRelu)
{
    __shared__ uint32_t As[128][20];
    __shared__ uint32_t Ws[128][20];

    const int tid = threadIdx.x;
    const int bm = blockIdx.y * 128, bn = blockIdx.x * 128;
    const int warp = tid >> 5, lane = tid & 31;
    const int wm = warp & 3, wn = warp >> 2;
    const int grp = lane >> 2, q = lane & 3;

    const int ldrow = tid >> 1;
    const int ldc0  = (tid & 1) * 8;

    float c[2][8][4];
    #pragma unroll
    for (int mi = 0; mi < 2; mi++)
        #pragma unroll
        for (int ni = 0; ni < 8; ni++)
            #pragma unroll
            for (int r = 0; r < 4; r++) c[mi][ni][r] = 0.f;

    for (int k0 = 0; k0 < K; k0 += 16) {
        {
            const float4* ap = reinterpret_cast<const float4*>(
                &A[(size_t)(bm + ldrow) * K + k0 + ldc0]);
            float4 v0 = ap[0], v1 = ap[1];
            As[ldrow][ldc0 + 0] = f2tf(v0.x);
            As[ldrow][ldc0 + 1] = f2tf(v0.y);
            As[ldrow][ldc0 + 2] = f2tf(v0.z);
            As[ldrow][ldc0 + 3] = f2tf(v0.w);
            As[ldrow][ldc0 + 4] = f2tf(v1.x);
            As[ldrow][ldc0 + 5] = f2tf(v1.y);
            As[ldrow][ldc0 + 6] = f2tf(v1.z);
            As[ldrow][ldc0 + 7] = f2tf(v1.w);
            const float4* wp = reinterpret_cast<const float4*>(
                &W[(size_t)(bn + ldrow) * K + k0 + ldc0]);
            float4 w0 = wp[0], w1 = wp[1];
            Ws[ldrow][ldc0 + 0] = f2tf(w0.x);
            Ws[ldrow][ldc0 + 1] = f2tf(w0.y);
            Ws[ldrow][ldc0 + 2] = f2tf(w0.z);
            Ws[ldrow][ldc0 + 3] = f2tf(w0.w);
            Ws[ldrow][ldc0 + 4] = f2tf(w1.x);
            Ws[ldrow][ldc0 + 5] = f2tf(w1.y);
            Ws[ldrow][ldc0 + 6] = f2tf(w1.z);
            Ws[ldrow][ldc0 + 7] = f2tf(w1.w);
        }
        __syncthreads();

        #pragma unroll
        for (int ks = 0; ks < 2; ks++) {
            const int kb = ks * 8;
            uint32_t af[2][4];
            #pragma unroll
            for (int mi = 0; mi < 2; mi++) {
                int m = wm * 32 + mi * 16 + grp;
                af[mi][0] = As[m    ][kb + q];
                af[mi][1] = As[m + 8][kb + q];
                af[mi][2] = As[m    ][kb + q + 4];
                af[mi][3] = As[m + 8][kb + q + 4];
            }
            uint32_t bf[8][2];
            #pragma unroll
            for (int ni = 0; ni < 8; ni++) {
                int n = wn * 64 + ni * 8 + grp;
                bf[ni][0] = Ws[n][kb + q];
                bf[ni][1] = Ws[n][kb + q + 4];
            }
            #pragma unroll
            for (int mi = 0; mi < 2; mi++)
                #pragma unroll
                for (int ni = 0; ni < 8; ni++)
                    mma_tf32(c[mi][ni], af[mi], bf[ni]);
        }
        __syncthreads();
    }

    #pragma unroll
    for (int mi = 0; mi < 2; mi++) {
        int r0 = bm + wm * 32 + mi * 16 + grp;
        #pragma unroll
        for (int ni = 0; ni < 8; ni++) {
            int col = bn + wn * 64 + ni * 8 + 2 * q;
            float b0 = bias[col], b1 = bias[col + 1];
            float v0 = c[mi][ni][0] + b0;
            float v1 = c[mi][ni][1] + b1;
            float v2 = c[mi][ni][2] + b0;
            float v3 = c[mi][ni][3] + b1;
            if (doRelu) {
                v0 = fmaxf(v0, 0.f); v1 = fmaxf(v1, 0.f);
                v2 = fmaxf(v2, 0.f); v3 = fmaxf(v3, 0.f);
            }
            reinterpret_cast<float2*>(&C[(size_t)r0 * N + col])[0]       = make_float2(v0, v1);
            reinterpret_cast<float2*>(&C[(size_t)(r0 + 8) * N + col])[0] = make_float2(v2, v3);
        }
    }
}

// ---------------- tf32 tensor-core flash attention, DH=32 --------------------
// block = 128 threads (4 warps); each warp owns a 16-row query tile (64/block).
// K-tile = 128 keys staged in smem (tf32, stride 36 => conflict-free fragments).
// grid: (LQ/64, B*H)
__global__ __launch_bounds__(128) void attn_tf32_kernel(
    const float* __restrict__ qk, const float* __restrict__ vbuf,
    float* __restrict__ out)
{
    const float scale = 0.17677669529663689f; // 1/sqrt(32)
    const int bh = blockIdx.y;
    const int b = bh >> 3, h = bh & 7;
    const int q0 = blockIdx.x * 64;
    const int tid = threadIdx.x;
    const int w = tid >> 5, lane = tid & 31;
    const int grp = lane >> 2, qd = lane & 3;

    __shared__ uint32_t Ks[128][36];
    __shared__ uint32_t Vs[128][36];

    // Q fragments (A operand), pre-scaled: rows w*16+grp, w*16+grp+8
    uint32_t qa[4][4];
    {
        const float* qp0 = qk + (size_t)(b * LQ_ + q0 + w * 16 + grp) * 512 + h * 32;
        const float* qp1 = qp0 + (size_t)8 * 512;
        #pragma unroll
        for (int kt = 0; kt < 4; kt++) {
            qa[kt][0] = f2tf(qp0[kt * 8 + qd]     * scale);
            qa[kt][1] = f2tf(qp1[kt * 8 + qd]     * scale);
            qa[kt][2] = f2tf(qp0[kt * 8 + qd + 4] * scale);
            qa[kt][3] = f2tf(qp1[kt * 8 + qd + 4] * scale);
        }
    }

    float o[4][4];
    #pragma unroll
    for (int dn = 0; dn < 4; dn++)
        #pragma unroll
        for (int r = 0; r < 4; r++) o[dn][r] = 0.f;
    float m0 = -1e30f, m1 = -1e30f, l0 = 0.f, l1 = 0.f;

    const int ldr = tid >> 3;           // 0..15
    const int ldc = (tid & 7) * 4;      // 0,4,...,28

    for (int kb = 0; kb < LQ_; kb += 128) {
        // stage K,V tiles (128x32) as tf32
        #pragma unroll
        for (int i = 0; i < 8; i++) {
            int row = ldr + i * 16;
            size_t gro = (size_t)(b * LQ_ + kb + row);
            float4 kv = *reinterpret_cast<const float4*>(qk + gro * 512 + 256 + h * 32 + ldc);
            float4 vv = *reinterpret_cast<const float4*>(vbuf + gro * 256 + h * 32 + ldc);
            uint4 kt4 = make_uint4(f2tf(kv.x), f2tf(kv.y), f2tf(kv.z), f2tf(kv.w));
            uint4 vt4 = make_uint4(f2tf(vv.x), f2tf(vv.y), f2tf(vv.z), f2tf(vv.w));
            *reinterpret_cast<uint4*>(&Ks[row][ldc]) = kt4;
            *reinterpret_cast<uint4*>(&Vs[row][ldc]) = vt4;
        }
        __syncthreads();

        // S = Q K^T : 16 x 128 per warp
        float s[16][4];
        #pragma unroll
        for (int nt = 0; nt < 16; nt++)
            #pragma unroll
            for (int r = 0; r < 4; r++) s[nt][r] = 0.f;

        #pragma unroll
        for (int kt = 0; kt < 4; kt++) {
            #pragma unroll
            for (int nt = 0; nt < 16; nt++) {
                uint32_t bf[2];
                bf[0] = Ks[nt * 8 + grp][kt * 8 + qd];
                bf[1] = Ks[nt * 8 + grp][kt * 8 + qd + 4];
                mma_tf32(s[nt], qa[kt], bf);
            }
        }

        // online softmax (rows grp -> regs 0,1 ; grp+8 -> regs 2,3)
        float mx0 = -1e30f, mx1 = -1e30f;
        #pragma unroll
        for (int nt = 0; nt < 16; nt++) {
            mx0 = fmaxf(mx0, fmaxf(s[nt][0], s[nt][1]));
            mx1 = fmaxf(mx1, fmaxf(s[nt][2], s[nt][3]));
        }
        mx0 = fmaxf(mx0, __shfl_xor_sync(0xffffffffu, mx0, 1));
        mx0 = fmaxf(mx0, __shfl_xor_sync(0xffffffffu, mx0, 2));
        mx1 = fmaxf(mx1, __shfl_xor_sync(0xffffffffu, mx1, 1));
        mx1 = fmaxf(mx1, __shfl_xor_sync(0xffffffffu, mx1, 2));

        float mn0 = fmaxf(m0, mx0), mn1 = fmaxf(m1, mx1);
        float c0 = __expf(m0 - mn0), c1 = __expf(m1 - mn1);
        m0 = mn0; m1 = mn1;
        l0 *= c0; l1 *= c1;
        #pragma unroll
        for (int dn = 0; dn < 4; dn++) {
            o[dn][0] *= c0; o[dn][1] *= c0;
            o[dn][2] *= c1; o[dn][3] *= c1;
        }

        // exp + convert to tf32 in place; sum the converted values
        float ps0 = 0.f, ps1 = 0.f;
        #pragma unroll
        for (int nt = 0; nt < 16; nt++) {
            float e0 = __uint_as_float(f2tf(__expf(s[nt][0] - mn0)));
            float e1 = __uint_as_float(f2tf(__expf(s[nt][1] - mn0)));
            float e2 = __uint_as_float(f2tf(__expf(s[nt][2] - mn1)));
            float e3 = __uint_as_float(f2tf(__expf(s[nt][3] - mn1)));
            ps0 += e0 + e1; ps1 += e2 + e3;
            s[nt][0] = e0; s[nt][1] = e1; s[nt][2] = e2; s[nt][3] = e3;
        }
        ps0 += __shfl_xor_sync(0xffffffffu, ps0, 1);
        ps0 += __shfl_xor_sync(0xffffffffu, ps0, 2);
        ps1 += __shfl_xor_sync(0xffffffffu, ps1, 1);
        ps1 += __shfl_xor_sync(0xffffffffu, ps1, 2);
        l0 += ps0; l1 += ps1;

        // O += P V : A fragments of P built via lane-quad shuffles
        const int base = lane & 28;
        const int src_lo = base | (qd >> 1);
        const int src_hi = src_lo + 2;
        const bool odd = (qd & 1);
        #pragma unroll
        for (int kt = 0; kt < 16; kt++) {
            float v0l = __shfl_sync(0xffffffffu, s[kt][0], src_lo);
            float v1l = __shfl_sync(0xffffffffu, s[kt][1], src_lo);
            float v2l = __shfl_sync(0xffffffffu, s[kt][2], src_lo);
            float v3l = __shfl_sync(0xffffffffu, s[kt][3], src_lo);
            float v0h = __shfl_sync(0xffffffffu, s[kt][0], src_hi);
            float v1h = __shfl_sync(0xffffffffu, s[kt][1], src_hi);
            float v2h = __shfl_sync(0xffffffffu, s[kt][2], src_hi);
            float v3h = __shfl_sync(0xffffffffu, s[kt][3], src_hi);
            uint32_t af[4];
            af[0] = __float_as_uint(odd ? v1l : v0l);
            af[1] = __float_as_uint(odd ? v3l : v2l);
            af[2] = __float_as_uint(odd ? v1h : v0h);
            af[3] = __float_as_uint(odd ? v3h : v2h);
            #pragma unroll
            for (int dn = 0; dn < 4; dn++) {
                uint32_t bf[2];
                bf[0] = Vs[kt * 8 + qd][dn * 8 + grp];
                bf[1] = Vs[kt * 8 + qd + 4][dn * 8 + grp];
                mma_tf32(o[dn], af, bf);
            }
        }
        __syncthreads();
    }

    float inv0 = 1.f / l0, inv1 = 1.f / l1;
    float* op0 = out + (size_t)(b * LQ_ + q0 + w * 16 + grp) * 256 + h * 32;
    float* op1 = op0 + (size_t)8 * 256;
    #pragma unroll
    for (int dn = 0; dn < 4; dn++) {
        reinterpret_cast<float2*>(op0 + dn * 8 + 2 * qd)[0] =
            make_float2(o[dn][0] * inv0, o[dn][1] * inv0);
        reinterpret_cast<float2*>(op1 + dn * 8 + 2 * qd)[0] =
            make_float2(o[dn][2] * inv1, o[dn][3] * inv1);
    }
}

// ---------------- fused residual + LayerNorm (D=256) ------------------------
__global__ __launch_bounds__(256) void add_ln_kernel(
    const float* __restrict__ a, const float* __restrict__ b,
    const float* __restrict__ g, const float* __restrict__ bet,
    float* __restrict__ out)
{
    int row = blockIdx.x;
    int t = threadIdx.x;
    size_t base = (size_t)row * 256;
    float x = a[base + t] + b[base + t];
    float s = x, sq = x * x;
    #pragma unroll
    for (int o = 16; o > 0; o >>= 1) {
        s  += __shfl_xor_sync(0xffffffffu, s, o);
        sq += __shfl_xor_sync(0xffffffffu, sq, o);
    }
    __shared__ float ss[8], ssq[8];
    int w = t >> 5, ln = t & 31;
    if (ln == 0) { ss[w] = s; ssq[w] = sq; }
    __syncthreads();
    float tot = 0.f, totq = 0.f;
    #pragma unroll
    for (int i = 0; i < 8; i++) { tot += ss[i]; totq += ssq[i]; }
    float mean = tot * (1.f / 256.f);
    float var  = totq * (1.f / 256.f) - mean * mean;
    out[base + t] = (x - mean) * rsqrtf(var + 1e-5f) * g[t] + bet[t];
}

// ---------------- softmax over 16 (per b,q,h) -------------------------------
__global__ void softmax16_kernel(float* __restrict__ w, int n) {
    int i = blockIdx.x * blockDim.x + threadIdx.x;
    if (i >= n) return;
    float4* p = reinterpret_cast<float4*>(w + (size_t)i * 16);
    float4 v[4];
    #pragma unroll
    for (int j = 0; j < 4; j++) v[j] = p[j];
    float mx = -1e30f;
    #pragma unroll
    for (int j = 0; j < 4; j++) {
        mx = fmaxf(mx, fmaxf(fmaxf(v[j].x, v[j].y), fmaxf(v[j].z, v[j].w)));
    }
    float sum = 0.f;
    #pragma unroll
    for (int j = 0; j < 4; j++) {
        v[j].x = __expf(v[j].x - mx); sum += v[j].x;
        v[j].y = __expf(v[j].y - mx); sum += v[j].y;
        v[j].z = __expf(v[j].z - mx); sum += v[j].z;
        v[j].w = __expf(v[j].w - mx); sum += v[j].w;
    }
    float inv = 1.f / sum;
    #pragma unroll
    for (int j = 0; j < 4; j++) {
        v[j].x *= inv; v[j].y *= inv; v[j].z *= inv; v[j].w *= inv;
        p[j] = v[j];
    }
}

// ---------------- deformable sampling ---------------------------------------
__device__ __forceinline__ float dtap(const float* __restrict__ value,
                                      int b, int start, int hl, int wl,
                                      int xi, int yi, int h, int lane) {
    if (xi < 0 || xi >= wl || yi < 0 || yi >= hl) return 0.f;
    int row = start + yi * wl + xi;
    return value[((size_t)(b * LV_ + row) * 8 + h) * 32 + lane];
}

__global__ __launch_bounds__(128) void deform_kernel(
    const float* __restrict__ refp, const float* __restrict__ off,
    const float* __restrict__ attw, const float* __restrict__ value,
    float* __restrict__ out)
{
    int wid = blockIdx.x * 4 + (threadIdx.x >> 5);
    int lane = threadIdx.x & 31;
    int h = wid & 7;
    int bq = wid >> 3;
    int b = bq >> 10;
    const int HLs[4] = {64, 32, 16, 8};
    float acc = 0.f;
    int start = 0;
    #pragma unroll
    for (int lvl = 0; lvl < 4; lvl++) {
        int hl = HLs[lvl], wl = HLs[lvl];
        float fwl = (float)wl, fhl = (float)hl;
        float refx = refp[(bq * 4 + lvl) * 2 + 0];
        float refy = refp[(bq * 4 + lvl) * 2 + 1];
        #pragma unroll
        for (int p = 0; p < 4; p++) {
            int oi = bq * 256 + ((h * 4 + lvl) * 4 + p) * 2;
            float ox = off[oi], oy = off[oi + 1];
            float aw = attw[(bq * 8 + h) * 16 + lvl * 4 + p];
            float locx = refx + ox / fwl;
            float locy = refy + oy / fhl;
            float x = locx * fwl - 0.5f;
            float y = locy * fhl - 0.5f;
            float x0 = floorf(x), y0 = floorf(y);
            float lx = x - x0, ly = y - y0;
            int x0i = (int)x0, y0i = (int)y0;
            float v00 = dtap(value, b, start, hl, wl, x0i,     y0i,     h, lane);
            float v01 = dtap(value, b, start, hl, wl, x0i + 1, y0i,     h, lane);
            float v10 = dtap(value, b, start, hl, wl, x0i,     y0i + 1, h, lane);
            float v11 = dtap(value, b, start, hl, wl, x0i + 1, y0i + 1, h, lane);
            float sx = v00 * (1.f - lx) * (1.f - ly) + v01 * lx * (1.f - ly)
                     + v10 * (1.f - lx) * ly         + v11 * lx * ly;
            acc = fmaf(aw, sx, acc);
        }
        start += hl * wl;
    }
    out[(size_t)bq * 256 + h * 32 + lane] = acc;
}

// ---------------- launcher ---------------------------------------------------
extern "C" void kernel_launch(void* const* d_in, const int* in_sizes, int n_in,
                              void* d_out, int out_size)
{
    const float* tgt       = (const float*)d_in[0];
    const float* query_pos = (const float*)d_in[1];
    const float* refp      = (const float*)d_in[2];
    const float* src       = (const float*)d_in[3];
    const float* in_proj_w = (const float*)d_in[4];
    const float* in_proj_b = (const float*)d_in[5];
    const float* out_proj_w= (const float*)d_in[6];
    const float* out_proj_b= (const float*)d_in[7];
    const float* norm2_g   = (const float*)d_in[8];
    const float* norm2_b   = (const float*)d_in[9];
    const float* value_w   = (const float*)d_in[10];
    const float* value_b   = (const float*)d_in[11];
    const float* off_w     = (const float*)d_in[12];
    const float* off_b     = (const float*)d_in[13];
    const float* attw_w    = (const float*)d_in[14];
    const float* attw_b    = (const float*)d_in[15];
    const float* outp_w    = (const float*)d_in[16];
    const float* outp_b    = (const float*)d_in[17];
    const float* norm1_g   = (const float*)d_in[18];
    const float* norm1_b   = (const float*)d_in[19];
    const float* lin1_w    = (const float*)d_in[20];
    const float* lin1_b    = (const float*)d_in[21];
    const float* lin2_w    = (const float*)d_in[22];
    const float* lin2_b    = (const float*)d_in[23];
    const float* norm3_g   = (const float*)d_in[24];
    const float* norm3_b   = (const float*)d_in[25];
    float* outp = (float*)d_out;

    float *q_, *qk_, *v_, *attn_, *proj_, *tgt1_, *tgt2_, *val_, *off_, *attw_, *samp_, *hid_;
    cudaGetSymbolAddress((void**)&q_,    g_q);
    cudaGetSymbolAddress((void**)&qk_,   g_qk);
    cudaGetSymbolAddress((void**)&v_,    g_v);
    cudaGetSymbolAddress((void**)&attn_, g_attn);
    cudaGetSymbolAddress((void**)&proj_, g_proj);
    cudaGetSymbolAddress((void**)&tgt1_, g_tgt1);
    cudaGetSymbolAddress((void**)&tgt2_, g_tgt2);
    cudaGetSymbolAddress((void**)&val_,  g_val);
    cudaGetSymbolAddress((void**)&off_,  g_off);
    cudaGetSymbolAddress((void**)&attw_, g_attw);
    cudaGetSymbolAddress((void**)&samp_, g_samp);
    cudaGetSymbolAddress((void**)&hid_,  g_hid);

    const int n4 = (BLQ * D_) / 4;

    add_kernel<<<(n4 + 255) / 256, 256>>>(tgt, query_pos, q_, n4);
    sgemm_tf32<<<dim3(4, BLQ / 128), 256>>>(q_, in_proj_w, in_proj_b, qk_, BLQ, 512, 256, 0);
    sgemm_tf32<<<dim3(2, BLQ / 128), 256>>>(tgt, in_proj_w + 512 * 256, in_proj_b + 512, v_, BLQ, 256, 256, 0);
    attn_tf32_kernel<<<dim3(LQ_ / 64, B_ * H_), 128>>>(qk_, v_, attn_);
    sgemm_tf32<<<dim3(2, BLQ / 128), 256>>>(attn_, out_proj_w, out_proj_b, proj_, BLQ, 256, 256, 0);
    add_ln_kernel<<<BLQ, 256>>>(tgt, proj_, norm2_g, norm2_b, tgt1_);
    add_kernel<<<(n4 + 255) / 256, 256>>>(tgt1_, query_pos, q_, n4);
    sgemm_tf32<<<dim3(2, BLV / 128), 256>>>(src, value_w, value_b, val_, BLV, 256, 256, 0);
    sgemm_tf32<<<dim3(2, BLQ / 128), 256>>>(q_, off_w, off_b, off_, BLQ, 256, 256, 0);
    sgemm_tf32<<<dim3(1, BLQ / 128), 256>>>(q_, attw_w, attw_b, attw_, BLQ, 128, 256, 0);
    softmax16_kernel<<<(BLQ * H_) / 256, 256>>>(attw_, BLQ * H_);
    deform_kernel<<<(BLQ * H_) / 4, 128>>>(refp, off_, attw_, val_, samp_);
    sgemm_tf32<<<dim3(2, BLQ / 128), 256>>>(samp_, outp_w, outp_b, proj_, BLQ, 256, 256, 0);
    add_ln_kernel<<<BLQ, 256>>>(tgt1_, proj_, norm1_g, norm1_b, tgt2_);
    sgemm_tf32<<<dim3(8, BLQ / 128), 256>>>(tgt2_, lin1_w, lin1_b, hid_, BLQ, 1024, 256, 1);
    sgemm_tf32<<<dim3(2, BLQ / 128), 256>>>(hid_, lin2_w, lin2_b, proj_, BLQ, 256, 1024, 0);
    add_ln_kernel<<<BLQ, 256>>>(tgt2_, proj_, norm3_g, norm3_b, outp);
}